// round 1
// baseline (speedup 1.0000x reference)
#include <cuda_runtime.h>
#include <cuda_bf16.h>
#include <cstdint>

// NeRF volume rendering compositing.
// rgb: [B, 64, 3] f32, sigma: [B, 64] f32
// out: [B*3] rgb_map followed by [B] depth_map (f32)
//
// One warp per ray; lane l owns samples (2l, 2l+1).
// Exclusive transmittance cumprod via warp Kogge-Stone product scan.

#ifndef NERF_S
#define NERF_S 64
#endif

__global__ __launch_bounds__(256) void nerf_render_kernel(
    const float* __restrict__ rgb,
    const float* __restrict__ sigma,
    float* __restrict__ out,
    int n_rays)
{
    const int gtid = blockIdx.x * blockDim.x + threadIdx.x;
    const int ray  = gtid >> 5;
    const int lane = threadIdx.x & 31;
    if (ray >= n_rays) return;

    // ---- loads (issue rgb early for MLP; both fully coalesced) ----
    const float2* rp = reinterpret_cast<const float2*>(
        rgb + (size_t)ray * (NERF_S * 3) + 6 * lane);
    float2 c0 = rp[0];   // r0 g0
    float2 c1 = rp[1];   // b0 r1
    float2 c2 = rp[2];   // g1 b1

    const float2 sg = *reinterpret_cast<const float2*>(
        sigma + (size_t)ray * NERF_S + 2 * lane);

    // ---- alpha / per-sample transmittance factor ----
    float a0 = 1.0f - __expf(-sg.x);
    float a1 = 1.0f - __expf(-sg.y);
    float t0 = 1.0f - a0 + 1e-10f;
    float t1 = 1.0f - a1 + 1e-10f;

    // ---- exclusive product scan over 64 samples (lane pair order) ----
    float p = t0 * t1;            // per-lane local product
    float incl = p;
    #pragma unroll
    for (int off = 1; off < 32; off <<= 1) {
        float v = __shfl_up_sync(0xffffffffu, incl, off);
        if (lane >= off) incl *= v;
    }
    float excl = __shfl_up_sync(0xffffffffu, incl, 1);
    if (lane == 0) excl = 1.0f;

    float T0 = excl;          // transmittance before sample 2l
    float T1 = excl * t0;     // before sample 2l+1
    float w0 = a0 * T0;
    float w1 = a1 * T1;

    // ---- weighted sums ----
    float r = w0 * c0.x + w1 * c1.y;
    float g = w0 * c0.y + w1 * c2.x;
    float b = w0 * c1.x + w1 * c2.y;

    const int s0 = 2 * lane;
    const float step = 4.0f / 63.0f;   // linspace(2, 6, 64)
    float tv0 = 2.0f + step * (float)s0;
    float tv1 = 2.0f + step * (float)(s0 + 1);
    float d = w0 * tv0 + w1 * tv1;

    // ---- warp reductions ----
    #pragma unroll
    for (int off = 16; off > 0; off >>= 1) {
        r += __shfl_xor_sync(0xffffffffu, r, off);
        g += __shfl_xor_sync(0xffffffffu, g, off);
        b += __shfl_xor_sync(0xffffffffu, b, off);
        d += __shfl_xor_sync(0xffffffffu, d, off);
    }

    if (lane == 0) {
        float* rgb_map = out;
        float* depth_map = out + (size_t)n_rays * 3;
        rgb_map[(size_t)ray * 3 + 0] = r;
        rgb_map[(size_t)ray * 3 + 1] = g;
        rgb_map[(size_t)ray * 3 + 2] = b;
        depth_map[ray] = d;
    }
}

extern "C" void kernel_launch(void* const* d_in, const int* in_sizes, int n_in,
                              void* d_out, int out_size)
{
    const float* rgb   = (const float*)d_in[0];   // [B, 64, 3]
    const float* sigma = (const float*)d_in[1];   // [B, 64]
    float* out = (float*)d_out;

    const int n_rays = in_sizes[1] / NERF_S;

    const int threads = 256;                 // 8 warps = 8 rays / block
    const int rays_per_block = threads / 32;
    const int blocks = (n_rays + rays_per_block - 1) / rays_per_block;
    nerf_render_kernel<<<blocks, threads>>>(rgb, sigma, out, n_rays);
}